// round 10
// baseline (speedup 1.0000x reference)
#include <cuda_runtime.h>

// RandomShiftsAug on GB300 — integer-shift copy with edge clamp.
// out[n,c,y,x] = in[n,c, clamp(y+sy-4,0,127), clamp(x+sx-4,0,127)]
//
// R9: cp.async staging, MLP=8, warp-autonomous (no CTA barrier).
//  Each warp owns 8 rows of one (n,c) image:
//   load : 8 cp.async.cg 16B copies per thread (global->smem, bypasses RF+L1).
//   sync : cp.async.wait_group 0 + __syncwarp (exchange is intra-warp).
//   store: per row, 4 coalesced STG.32 from stride-1 (conflict-free) smem.

#define PADV 4
#define CB   9
#define HB   128
#define RW   8            // rows per warp

__global__ void __launch_bounds__(256)
random_shift_cpasync_kernel(const float* __restrict__ x,
                            const int* __restrict__ shift,
                            float* __restrict__ out)
{
    __shared__ float srow[8][RW][HB];   // 8 warps * 8 rows * 512B = 32 KB

    int w = threadIdx.x >> 5;
    int l = threadIdx.x & 31;

    int gwarp = blockIdx.x * 8 + w;    // 73728 warps total
    int grp   = gwarp & 15;            // 16 row-octets per image
    int nc    = gwarp >> 4;            // n*9 + c
    int y0    = grp << 3;
    int n     = nc / CB;

    int sx = shift[2 * n]     - PADV;  // warp-uniform
    int sy = shift[2 * n + 1] - PADV;

    const float* __restrict__ img = x + (long long)nc * (HB * HB);

    unsigned sm_base = (unsigned)__cvta_generic_to_shared(&srow[w][0][0]);

    // ---- stage 8 source rows: 8 cp.async in flight per thread ----
    #pragma unroll
    for (int r = 0; r < RW; r++) {
        int ys = y0 + r + sy;
        ys = ys < 0 ? 0 : (ys > HB - 1 ? HB - 1 : ys);
        const float* gp = img + ys * HB + (l << 2);
        unsigned sp = sm_base + ((r * HB + (l << 2)) << 2);
        asm volatile("cp.async.cg.shared.global [%0], [%1], 16;\n"
                     :: "r"(sp), "l"(gp) : "memory");
    }
    asm volatile("cp.async.commit_group;\n" ::: "memory");
    asm volatile("cp.async.wait_group 0;\n" ::: "memory");
    __syncwarp();

    // ---- emit 8 shifted rows ----
    float* __restrict__ dst0 = out + ((long long)nc * HB + y0) * HB;

    #pragma unroll
    for (int r = 0; r < RW; r++) {
        float* __restrict__ dst = dst0 + r * HB;
        #pragma unroll
        for (int m = 0; m < 4; m++) {
            int col = l + (m << 5);
            int sc  = col + sx;
            sc = sc < 0 ? 0 : (sc > HB - 1 ? HB - 1 : sc);
            __stcs(dst + col, srow[w][r][sc]);
        }
    }
}

extern "C" void kernel_launch(void* const* d_in, const int* in_sizes, int n_in,
                              void* d_out, int out_size)
{
    const float* x     = (const float*)d_in[0];
    const int*   shift = (const int*)d_in[1];
    float*       out   = (float*)d_out;

    // 4608 images * 16 row-octets = 73728 warps / 8 per CTA = 9216 CTAs
    random_shift_cpasync_kernel<<<9216, 256>>>(x, shift, out);
}

// round 11
// speedup vs baseline: 1.0163x; 1.0163x over previous
#include <cuda_runtime.h>

// RandomShiftsAug on GB300 — integer-shift copy with edge clamp.
// out[n,c,y,x] = in[n,c, clamp(y+sy-4,0,127), clamp(x+sx-4,0,127)]
//
// R11: register+shuffle shift, zero shared memory, no barriers.
//  Warp owns 4 rows of one (n,c) image. Lane l holds aligned quad l of the
//  row (1 LDG.128). Output quad cols 4l+sx..+3 are consecutive, so each
//  output word is a scalar shfl of a WARP-UNIFORM component ((sx+j)&3) from
//  lane (4l+sx+j)>>2. Edge clamp: first/last row values via 2 shfls + 8
//  predicated selects (only lanes 0/31 ever trigger).
//  Per 512B row: 4 LDG.128 + 4 STG.128 wavefronts — pure-copy L1 cost.

#define PADV 4
#define CB   9
#define HB   128
#define RW   4
#define FULLM 0xFFFFFFFFu

__global__ void __launch_bounds__(256)
random_shift_shfl_kernel(const float* __restrict__ x,
                         const int* __restrict__ shift,
                         float* __restrict__ out)
{
    int w = threadIdx.x >> 5;
    int l = threadIdx.x & 31;

    int gwarp = blockIdx.x * 8 + w;    // 147456 warps
    int grp   = gwarp & 31;            // 32 row-quartets per image
    int nc    = gwarp >> 5;            // n*9 + c
    int y0    = grp << 2;
    int n     = nc / CB;

    int sx = shift[2 * n]     - PADV;  // warp-uniform, in [-4,4]
    int sy = shift[2 * n + 1] - PADV;

    const float4* __restrict__ img4 = reinterpret_cast<const float4*>(x);
    int ibase = nc * (HB * HB / 4);    // fits in 32-bit

    // ---- 4 aligned LDG.128 in flight ----
    float4 A[RW];
    #pragma unroll
    for (int r = 0; r < RW; r++) {
        int ys = y0 + r + sy;
        ys = ys < 0 ? 0 : (ys > HB - 1 ? HB - 1 : ys);
        A[r] = __ldcs(img4 + ibase + ys * (HB / 4) + l);
    }

    int c0 = (l << 2) + sx;            // first source col of my output quad
    int q0 = c0 >> 2;                  // source lane (arith shift = floor)
    int qa = q0 < 0 ? 0 : (q0 > 31 ? 31 : q0);
    int qb = q0 + 1 > 31 ? 31 : q0 + 1;      // q0+1 >= 0 always
    int rot = sx & 3;                  // warp-uniform rotation

    float4* __restrict__ dst4 =
        reinterpret_cast<float4*>(out) + (nc * HB + y0) * (HB / 4) + l;

    #pragma unroll
    for (int r = 0; r < RW; r++) {
        float4 a = A[r];
        float o0, o1, o2, o3;
        switch (rot) {                 // warp-uniform branch
        case 0:
            o0 = __shfl_sync(FULLM, a.x, qa); o1 = __shfl_sync(FULLM, a.y, qa);
            o2 = __shfl_sync(FULLM, a.z, qa); o3 = __shfl_sync(FULLM, a.w, qa);
            break;
        case 1:
            o0 = __shfl_sync(FULLM, a.y, qa); o1 = __shfl_sync(FULLM, a.z, qa);
            o2 = __shfl_sync(FULLM, a.w, qa); o3 = __shfl_sync(FULLM, a.x, qb);
            break;
        case 2:
            o0 = __shfl_sync(FULLM, a.z, qa); o1 = __shfl_sync(FULLM, a.w, qa);
            o2 = __shfl_sync(FULLM, a.x, qb); o3 = __shfl_sync(FULLM, a.y, qb);
            break;
        default:
            o0 = __shfl_sync(FULLM, a.w, qa); o1 = __shfl_sync(FULLM, a.x, qb);
            o2 = __shfl_sync(FULLM, a.y, qb); o3 = __shfl_sync(FULLM, a.z, qb);
            break;
        }

        // Edge clamp values (computed convergent; selected only on lanes 0/31).
        float first = __shfl_sync(FULLM, a.x, 0);    // col 0
        float last  = __shfl_sync(FULLM, a.w, 31);   // col 127

        if (c0     < 0) o0 = first; else if (c0     > HB - 1) o0 = last;
        if (c0 + 1 < 0) o1 = first; else if (c0 + 1 > HB - 1) o1 = last;
        if (c0 + 2 < 0) o2 = first; else if (c0 + 2 > HB - 1) o2 = last;
        if (c0 + 3 < 0) o3 = first; else if (c0 + 3 > HB - 1) o3 = last;

        float4 v; v.x = o0; v.y = o1; v.z = o2; v.w = o3;
        __stcs(dst4 + r * (HB / 4), v);
    }
}

extern "C" void kernel_launch(void* const* d_in, const int* in_sizes, int n_in,
                              void* d_out, int out_size)
{
    const float* x     = (const float*)d_in[0];
    const int*   shift = (const int*)d_in[1];
    float*       out   = (float*)d_out;

    // 4608 images * 32 row-quartets = 147456 warps / 8 per CTA = 18432 CTAs
    random_shift_shfl_kernel<<<18432, 256>>>(x, shift, out);
}